// round 7
// baseline (speedup 1.0000x reference)
#include <cuda_runtime.h>
#include <math.h>

#define TPB     128
#define NGROUPS 4
#define GSIZE   32                // l-chunks per block (= threads per n-group)
#define CHUNK   32                // l's per thread
#define NPACK   16                // packed f32x2 accumulators

// ---- packed f32x2 helpers (PTX-only) ----
__device__ __forceinline__ unsigned long long pack2(float lo, float hi) {
    unsigned long long r;
    asm("mov.b64 %0, {%1, %2};" : "=l"(r) : "f"(lo), "f"(hi));
    return r;
}
__device__ __forceinline__ void unpack2(unsigned long long v, float& lo, float& hi) {
    asm("mov.b64 {%0, %1}, %2;" : "=f"(lo), "=f"(hi) : "l"(v));
}
__device__ __forceinline__ unsigned long long fma2(unsigned long long a,
                                                   unsigned long long b,
                                                   unsigned long long c) {
    unsigned long long d;
    asm("fma.rn.f32x2 %0, %1, %2, %3;" : "=l"(d) : "l"(a), "l"(b), "l"(c));
    return d;
}
__device__ __forceinline__ unsigned long long mul2(unsigned long long a,
                                                   unsigned long long b) {
    unsigned long long d;
    asm("mul.rn.f32x2 %0, %1, %2;" : "=l"(d) : "l"(a), "l"(b));
    return d;
}
__device__ __forceinline__ unsigned long long add2(unsigned long long a,
                                                   unsigned long long b) {
    unsigned long long d;
    asm("add.rn.f32x2 %0, %1, %2;" : "=l"(d) : "l"(a), "l"(b));
    return d;
}

// 3-term Cody-Waite reduction of x mod 2*pi (exact FMAs for q <= ~8K)
__device__ __forceinline__ float reduce_2pi(float x) {
    const float INV2PI = 0.15915494309189535f;
    const float C1 = 6.28125f;
    const float C2 = 0.0019350051879882812f;
    const float C3 = 3.0197e-7f;
    float q = rintf(x * INV2PI);
    float r = fmaf(q, -C1, x);
    r = fmaf(q, -C2, r);
    r = fmaf(q, -C3, r);
    return r;
}

// dynamic smem layout (bytes):
//   sT  : float2[N*GSIZE]   seed table, 16384
//   sA  : float4[N]         (log|a|, arg a, log|w|, arg w)
//   sB  : float4[N]         (a.re, a.im, tr, det)
//   sC2 : float4[N]         (tr2, tr2, det2, det2)
//   sCC : float4[N*5]       chain consts (duplicated pairs)
#define OFF_T   0
#define OFF_A   (OFF_T  + 64 * GSIZE * 8)
#define OFF_B   (OFF_A  + 64 * 16)
#define OFF_C2  (OFF_B  + 64 * 16)
#define OFF_CC  (OFF_C2 + 64 * 16)
#define SMEM_BYTES (OFF_CC + 64 * 5 * 16)

__global__ void __launch_bounds__(TPB, 6)
lssl_table_gchain_kernel(
    const float* __restrict__ Lre, const float* __restrict__ Lim,
    const float* __restrict__ Bre, const float* __restrict__ Bim,
    const float* __restrict__ Cre, const float* __restrict__ Cim,
    const float* __restrict__ Dp,  const float* __restrict__ logdt,
    float* __restrict__ out, int N, int L, int d_model)
{
    extern __shared__ char smem[];
    float2* sT  = (float2*)(smem + OFF_T);
    float4* sA  = (float4*)(smem + OFF_A);
    float4* sB  = (float4*)(smem + OFF_B);
    float4* sC2 = (float4*)(smem + OFF_C2);
    float4* sCC = (float4*)(smem + OFF_CC);

    __shared__ unsigned long long red[NGROUPS - 1][GSIZE][NPACK + 1];

    const int d = blockIdx.x;
    const int t = threadIdx.x;

    // ---- Phase 1: per-(d,n) constants ----
    for (int n = t; n < N; n += TPB) {
        const int idx = d * N + n;
        float lr = Lre[idx], li = Lim[idx];
        float sp = fmaxf(lr, 0.0f) + log1pf(expf(-fabsf(lr)));  // softplus
        float lam_re = -sp, lam_im = li;
        float dt = expf(logdt[d]);

        float hre = 0.5f * dt * lam_re;
        float him = 0.5f * dt * lam_im;
        float dre = 1.0f - hre;
        float dim = -him;
        float inv = 1.0f / (dre * dre + dim * dim);

        float nre = 1.0f + hre, nim = him;
        float are = (nre * dre + nim * dim) * inv;   // a_bar
        float aim = (nim * dre - nre * dim) * inv;

        float br = Bre[idx], bi = Bim[idx];
        float bbre = dt * inv * (br * dre + bi * dim);
        float bbim = dt * inv * (bi * dre - br * dim);
        float cr = Cre[idx], ci = Cim[idx];
        float wre = cr * bbre - ci * bbim;           // w = C*b_bar
        float wim = cr * bbim + ci * bbre;

        float mag2 = are * are + aim * aim;
        float tr  = are + are;                       // 2 Re(a)
        float det = -mag2;                           // -|a|^2
        float tr2  = fmaf(tr, tr, 2.0f * det);
        float det2 = -det * det;
        float tr4  = fmaf(tr2, tr2, 2.0f * det2);

        // scaled-chain constants: c = |a|^4 = det^2 ; trp = tr4/c
        float c1 = det * det;
        float invc = 1.0f / c1;
        float trp = tr4 * invc;
        float c2v = c1 * c1;
        float c3v = c2v * c1;
        float c4v = c2v * c2v;
        float c5v = c4v * c1;
        float c6v = c3v * c3v;
        float c7v = c6v * c1;

        float wmag2 = wre * wre + wim * wim;
        sA[n]  = make_float4(0.5f * logf(mag2), atan2f(aim, are),
                             0.5f * logf(wmag2), atan2f(wim, wre));
        sB[n]  = make_float4(are, aim, tr, det);
        sC2[n] = make_float4(tr2, tr2, det2, det2);
        // sign pattern s_j = [+,+,-,-,+,+,-,-] -> cs_j = s_j * c^j
        sCC[n * 5 + 0] = make_float4(trp, trp, -trp, -trp);   // (trp2 | trn2)
        sCC[n * 5 + 1] = make_float4(invc, invc, -c2v, -c2v); // (invc2 | cs2)
        sCC[n * 5 + 2] = make_float4(-c3v, -c3v, c4v, c4v);   // (cs3 | cs4)
        sCC[n * 5 + 3] = make_float4(c5v, c5v, -c6v, -c6v);   // (cs5 | cs6)
        sCC[n * 5 + 4] = make_float4(-c7v, -c7v, 0.f, 0.f);   // (cs7 | -)
    }

    if (blockIdx.y == 0 && t == 0) {
        out[(size_t)d_model * (size_t)L + d] = Dp[d];  // D passthrough
    }
    __syncthreads();

    // ---- Phase 1.5: seed table T[n][k] = w * a^{(by*GSIZE+k)*CHUNK} ----
    // Same exp/sincos formula as before -> preserves reference fp32 semantics.
    for (int idx = t; idx < N * GSIZE; idx += TPB) {
        int n = idx >> 5;          // GSIZE = 32
        int k = idx & (GSIZE - 1);
        float4 A = sA[n];
        float fl0 = (float)((blockIdx.y * GSIZE + k) * CHUNK);
        float e  = __expf(fmaf(fl0, A.x, A.z));
        float ph = reduce_2pi(fl0 * A.y) + A.w;
        float sn, cs;
        __sincosf(ph, &sn, &cs);
        sT[idx] = make_float2(e * cs, e * sn);
    }
    __syncthreads();

    // ---- Phase 2: NGROUPS n-groups over this block's l-range ----
    const int grp = t / GSIZE;     // == warp id
    const int tg  = t % GSIZE;
    const int l0  = (blockIdx.y * GSIZE + tg) * CHUNK;
    const int nper = N / NGROUPS;
    const int n_begin = grp * nper;
    const int n_end   = n_begin + nper;

    unsigned long long acc[NPACK];
#pragma unroll
    for (int m = 0; m < NPACK; m++) acc[m] = 0ull;

    if (l0 < L) {
        const ulonglong2* cC2 = (const ulonglong2*)sC2;
        const ulonglong2* cCC = (const ulonglong2*)sCC;

        for (int n = n_begin; n < n_end; n++) {
            const float2 q  = sT[(n << 5) + tg];   // seed: w * a^{l0}
            const float4 B4 = sB[n];
            const ulonglong2 c2 = cC2[n];          // (tr2p, det2p)
            const ulonglong2 t0 = cCC[n * 5 + 0];  // (trp2, trn2)
            const ulonglong2 t1 = cCC[n * 5 + 1];  // (invc2, cs2)
            const ulonglong2 t2 = cCC[n * 5 + 2];  // (cs3, cs4)
            const ulonglong2 t3 = cCC[n * 5 + 3];  // (cs5, cs6)
            const ulonglong2 t4 = cCC[n * 5 + 4];  // (cs7, -)

            // s_l = Re(q * a^{l-l0})
            float s0 = q.x;
            float s1 = fmaf(q.x, B4.x, -(q.y * B4.y));
            float s2 = fmaf(B4.z, s1, B4.w * s0);
            float s3 = fmaf(B4.z, s2, B4.w * s1);

            unsigned long long u0 = pack2(s0, s1);
            unsigned long long u1 = pack2(s2, s3);
            unsigned long long u2 = fma2(c2.x, u1, mul2(c2.y, u0));
            unsigned long long u3 = fma2(c2.x, u2, mul2(c2.y, u1));

            acc[0] = add2(acc[0], u0);
            acc[1] = add2(acc[1], u1);
            acc[2] = add2(acc[2], u2);
            acc[3] = add2(acc[3], u3);

            // twin scaled chains: g_{j+1} = (+/-trp)*g_j + g_{j-1}; acc += cs_j * g_j
            unsigned long long gv0 = u0, gv1 = mul2(u2, t1.x);
            unsigned long long gw0 = u1, gw1 = mul2(u3, t1.x);

            unsigned long long gv2 = fma2(t0.y, gv1, gv0);   // j=1: -trp
            unsigned long long gw2 = fma2(t0.y, gw1, gw0);
            acc[4] = fma2(t1.y, gv2, acc[4]);
            acc[5] = fma2(t1.y, gw2, acc[5]);

            unsigned long long gv3 = fma2(t0.x, gv2, gv1);   // j=2: +trp
            unsigned long long gw3 = fma2(t0.x, gw2, gw1);
            acc[6] = fma2(t2.x, gv3, acc[6]);
            acc[7] = fma2(t2.x, gw3, acc[7]);

            unsigned long long gv4 = fma2(t0.y, gv3, gv2);   // j=3: -trp
            unsigned long long gw4 = fma2(t0.y, gw3, gw2);
            acc[8] = fma2(t2.y, gv4, acc[8]);
            acc[9] = fma2(t2.y, gw4, acc[9]);

            unsigned long long gv5 = fma2(t0.x, gv4, gv3);   // j=4: +trp
            unsigned long long gw5 = fma2(t0.x, gw4, gw3);
            acc[10] = fma2(t3.x, gv5, acc[10]);
            acc[11] = fma2(t3.x, gw5, acc[11]);

            unsigned long long gv6 = fma2(t0.y, gv5, gv4);   // j=5: -trp
            unsigned long long gw6 = fma2(t0.y, gw5, gw4);
            acc[12] = fma2(t3.y, gv6, acc[12]);
            acc[13] = fma2(t3.y, gw6, acc[13]);

            unsigned long long gv7 = fma2(t0.x, gv6, gv5);   // j=6: +trp
            unsigned long long gw7 = fma2(t0.x, gw6, gw5);
            acc[14] = fma2(t4.x, gv7, acc[14]);
            acc[15] = fma2(t4.x, gw7, acc[15]);
        }

        if (grp > 0) {
#pragma unroll
            for (int m = 0; m < NPACK; m++) red[grp - 1][tg][m] = acc[m];
        }
    }
    __syncthreads();

    if (grp == 0 && l0 < L) {
#pragma unroll
        for (int g = 0; g < NGROUPS - 1; g++) {
#pragma unroll
            for (int m = 0; m < NPACK; m++) acc[m] = add2(acc[m], red[g][tg][m]);
        }

        float* Kout = out + (size_t)d * (size_t)L + l0;
        if (l0 + CHUNK <= L) {
#pragma unroll
            for (int m = 0; m < NPACK; m++) {
                *reinterpret_cast<unsigned long long*>(Kout + 2 * m) = acc[m];
            }
        } else {
#pragma unroll
            for (int m = 0; m < NPACK; m++) {
                float lo, hi;
                unpack2(acc[m], lo, hi);
                if (l0 + 2 * m     < L) Kout[2 * m]     = lo;
                if (l0 + 2 * m + 1 < L) Kout[2 * m + 1] = hi;
            }
        }
    }
}

extern "C" void kernel_launch(void* const* d_in, const int* in_sizes, int n_in,
                              void* d_out, int out_size)
{
    const float* Lre   = (const float*)d_in[0];
    const float* Lim   = (const float*)d_in[1];
    const float* Bre   = (const float*)d_in[2];
    const float* Bim   = (const float*)d_in[3];
    const float* Cre   = (const float*)d_in[4];
    const float* Cim   = (const float*)d_in[5];
    const float* Dp    = (const float*)d_in[6];
    const float* logdt = (const float*)d_in[7];
    float* out = (float*)d_out;

    const int d_model = in_sizes[6];                 // 512
    const int N = in_sizes[0] / d_model;             // 64
    const int L = (out_size - d_model) / d_model;    // 2048

    const int per_block_l = GSIZE * CHUNK;           // 1024
    const int gridy = (L + per_block_l - 1) / per_block_l;  // 2

    dim3 grid(d_model, gridy);
    lssl_table_gchain_kernel<<<grid, TPB, SMEM_BYTES>>>(
        Lre, Lim, Bre, Bim, Cre, Cim, Dp, logdt, out, N, L, d_model);
}